// round 10
// baseline (speedup 1.0000x reference)
#include <cuda_runtime.h>
#include <cstdint>

#define BB     16
#define NIN    1024
#define MM     512
#define NCHUNK 16
#define CHUNK  (NIN / NCHUNK)   // 64
#define BPG    2                // batches per CTA
#define GRID   (NCHUNK * (BB / BPG))   // 128 CTAs, all resident
#define THREADS 544             // 16 producer warps + 1 reducer warp
#define LOG2E  1.4426950408889634f
#define LN_EPS 1e-5f

// Named barriers (id 0 reserved for __syncthreads). Count = 544 each
// (512 producer arrivals + 32 reducer syncs, or 32 + 512 for READY).
#define BAR_FULL0 1
#define BAR_FULL1 2
#define BAR_RDY0  3
#define BAR_RDY1  4

// Dynamic smem layout
#define SM_XSD   0                                   // u64[BPG][CHUNK][16] = 16384
#define SM_VQS   16384                               // u64[8][512]         = 32768
#define SM_EBUF  49152                               // f32[2][BPG][512]    = 8192
#define SM_SS    57344                               // f32[2][BPG]         = 16
#define SM_TOTAL 57360

typedef unsigned long long u64;

__device__ float g_partial[NCHUNK * BB * MM * 16];
__device__ unsigned int g_cnt1 = 0;
__device__ unsigned int g_cnt2 = 0;

__device__ __forceinline__ u64 pack2(float lo, float hi) {
    u64 r; asm("mov.b64 %0,{%1,%2};" : "=l"(r) : "f"(lo), "f"(hi)); return r;
}
__device__ __forceinline__ void unpack2(u64 v, float& lo, float& hi) {
    asm("mov.b64 {%0,%1},%2;" : "=f"(lo), "=f"(hi) : "l"(v));
}
__device__ __forceinline__ u64 fma2(u64 a, u64 b, u64 c) {
    u64 d; asm("fma.rn.f32x2 %0,%1,%2,%3;" : "=l"(d) : "l"(a), "l"(b), "l"(c)); return d;
}
__device__ __forceinline__ u64 add2(u64 a, u64 b) {
    u64 d; asm("add.rn.f32x2 %0,%1,%2;" : "=l"(d) : "l"(a), "l"(b)); return d;
}
__device__ __forceinline__ u64 mul2(u64 a, u64 b) {
    u64 d; asm("mul.rn.f32x2 %0,%1,%2;" : "=l"(d) : "l"(a), "l"(b)); return d;
}
__device__ __forceinline__ float ex2f(float x) {
    float y; asm("ex2.approx.f32 %0,%1;" : "=f"(y) : "f"(x)); return y;
}
__device__ __forceinline__ float rcpf(float x) {
    float y; asm("rcp.approx.f32 %0,%1;" : "=f"(y) : "f"(x)); return y;
}
__device__ __forceinline__ void stcs(float* p, float v) {
    asm volatile("st.global.cs.f32 [%0],%1;" :: "l"(p), "f"(v) : "memory");
}
__device__ __forceinline__ void bar_arrive(int id) {
    asm volatile("bar.arrive %0, %1;" :: "r"(id), "r"(THREADS) : "memory");
}
__device__ __forceinline__ void bar_wait(int id) {
    asm volatile("bar.sync %0, %1;" :: "r"(id), "r"(THREADS) : "memory");
}

// Warp-specialized fused kernel.
// Producers (warps 0-15, thread = m): pose -> exp -> agreement; STS raw exp(ag);
// bar.arrive(FULL). Consume S one iteration late (staged raw e2 + scalar factors,
// zero extra packed-FMA) guarded by bar.sync(READY) that the reducer fires early.
// Reducer (warp 16): waits FULL, sums the 512 exp(ag) per b, publishes S, fires
// READY. Producers have NO shuffle chains and no full-rendezvous barriers ->
// warps drift, FMA and MUFU windows overlap across warps.
__global__ __launch_bounds__(THREADS, 1)
void caps_fused(const float* __restrict__ x,     // [B, NIN, 16]
                const float* __restrict__ w,     // [NIN, 4, 4, MM]
                const float* __restrict__ V,     // [MM, 16]
                const float* __restrict__ gamma,
                const float* __restrict__ beta,
                float* __restrict__ nv_out,      // [B*MM, 16]
                float* __restrict__ agree_out)   // [B, NIN, MM]
{
    extern __shared__ char sm[];
    u64   (*xsd)[CHUNK][16] = (u64 (*)[CHUNK][16])(sm + SM_XSD);
    u64   (*vqs)[MM]        = (u64 (*)[MM])(sm + SM_VQS);
    float (*ebuf)[BPG][MM]  = (float (*)[BPG][MM])(sm + SM_EBUF);
    float (*sS)[BPG]        = (float (*)[BPG])(sm + SM_SS);

    const int tid   = threadIdx.x;
    const int wid   = tid >> 5;
    const int lane  = tid & 31;
    const int chunk = blockIdx.x % NCHUNK;
    const int bp    = blockIdx.x / NCHUNK;
    const int b0    = bp * BPG;
    const int n0    = chunk * CHUNK;

    // Stage + rescale + duplicate x into shared (all 544 threads help).
    for (int idx = tid; idx < BPG * CHUNK * 16; idx += THREADS) {
        const int bb  = idx / (CHUNK * 16);
        const int rem = idx % (CHUNK * 16);
        const int i   = rem >> 4;
        const int j   = rem & 15;
        const float v = x[(((size_t)(b0 + bb) * NIN) + n0 + i) * 16 + j] * LOG2E;
        xsd[bb][i][j] = pack2(v, v);
    }
    // Transposed packed query: vqs[k][m] = {V[m][2k], V[m][2k+1]} (LDS.64 conflict-free).
    if (tid < MM) {
        const float* vm = V + (size_t)tid * 16;
#pragma unroll
        for (int k = 0; k < 8; k++) vqs[k][tid] = pack2(vm[2 * k], vm[2 * k + 1]);
    }
    if (tid < 2 * BPG) ((float*)sS)[tid] = 1.0f;   // seed both S buffers
    __syncthreads();

    if (wid < 16) {
        // ---------------- Producer ----------------
        u64 acc2[BPG][8];   // running nv accumulator (u64[8] == float[16])
        u64 E[BPG][8];      // staged RAW e2 from the previous iteration
        float eag_p[BPG], inv_p[BPG];
#pragma unroll
        for (int bb = 0; bb < BPG; bb++) {
#pragma unroll
            for (int k = 0; k < 8; k++) { acc2[bb][k] = 0ull; E[bb][k] = 0ull; }
            eag_p[bb] = 0.f; inv_p[bb] = 1.f;
        }

        const float* wbase = w + (size_t)n0 * (16 * MM) + tid;
        float wn[16];
#pragma unroll
        for (int s = 0; s < 16; s++) wn[s] = wbase[(size_t)s * MM];

        for (int i = 0; i < CHUNK; i++) {
            // ---- Consume S_{i-1} (READY fired by reducer well before). ----
            bar_wait(BAR_RDY0 + ((i + 1) & 1));
            {
                const float S0 = sS[(i + 1) & 1][0];
                const float S1 = sS[(i + 1) & 1][1];
                const float s0 = eag_p[0] * inv_p[0] * rcpf(S0);
                const float s1 = eag_p[1] * inv_p[1] * rcpf(S1);
                const u64 s0d = pack2(s0, s0);
                const u64 s1d = pack2(s1, s1);
#pragma unroll
                for (int k = 0; k < 8; k++) {
                    acc2[0][k] = fma2(s0d, E[0][k], acc2[0][k]);
                    acc2[1][k] = fma2(s1d, E[1][k], acc2[1][k]);
                }
            }

            // ---- Pack current w; prefetch next iteration's w. ----
            u64 wpair[8];
#pragma unroll
            for (int k = 0; k < 8; k++) wpair[k] = pack2(wn[2 * k], wn[2 * k + 1]);
            if (i + 1 < CHUNK) {
                const float* wp = wbase + (size_t)(i + 1) * 16 * MM;
#pragma unroll
                for (int s = 0; s < 16; s++) wn[s] = wp[(size_t)s * MM];
            }

            // ---- Pose -> exp -> agreement; stage raw e2 + scalars; STS exp(ag). ----
#pragma unroll
            for (int bb = 0; bb < BPG; bb++) {
                u64 t2[8];
#pragma unroll
                for (int a = 0; a < 4; a++) {
#pragma unroll
                    for (int dp = 0; dp < 2; dp++) {
                        u64 acc = mul2(xsd[bb][i][a * 4 + 0], wpair[0 * 2 + dp]);
                        acc = fma2(xsd[bb][i][a * 4 + 1], wpair[1 * 2 + dp], acc);
                        acc = fma2(xsd[bb][i][a * 4 + 2], wpair[2 * 2 + dp], acc);
                        acc = fma2(xsd[bb][i][a * 4 + 3], wpair[3 * 2 + dp], acc);
                        t2[a * 2 + dp] = acc;
                    }
                }
#pragma unroll
                for (int k = 0; k < 8; k++) {
                    float lo, hi; unpack2(t2[k], lo, hi);
                    E[bb][k] = pack2(ex2f(lo), ex2f(hi));
                }
                u64 s01 = add2(add2(E[bb][0], E[bb][1]), add2(E[bb][2], E[bb][3]));
                u64 s23 = add2(add2(E[bb][4], E[bb][5]), add2(E[bb][6], E[bb][7]));
                u64 st  = add2(s01, s23);
                float slo, shi; unpack2(st, slo, shi);
                const float inv = rcpf(slo + shi);
                u64 g = mul2(E[bb][0], vqs[0][tid]);
#pragma unroll
                for (int k = 1; k < 8; k++) g = fma2(E[bb][k], vqs[k][tid], g);
                float glo, ghi; unpack2(g, glo, ghi);
                const float ag = (glo + ghi) * inv;
                stcs(agree_out + (((size_t)(b0 + bb) * NIN) + n0 + i) * MM + tid, ag);
                const float e = ex2f(ag * LOG2E);   // |ag| <= 1, max-free safe
                eag_p[bb] = e;
                inv_p[bb] = inv;
                ebuf[i & 1][bb][tid] = e;           // raw partial for the reducer
            }
            bar_arrive(BAR_FULL0 + (i & 1));        // non-blocking
        }

        // Final consume for iteration CHUNK-1.
        bar_wait(BAR_RDY0 + ((CHUNK - 1) & 1));
        {
            const float S0 = sS[(CHUNK - 1) & 1][0];
            const float S1 = sS[(CHUNK - 1) & 1][1];
            const float s0 = eag_p[0] * inv_p[0] * rcpf(S0);
            const float s1 = eag_p[1] * inv_p[1] * rcpf(S1);
            const u64 s0d = pack2(s0, s0);
            const u64 s1d = pack2(s1, s1);
#pragma unroll
            for (int k = 0; k < 8; k++) {
                acc2[0][k] = fma2(s0d, E[0][k], acc2[0][k]);
                acc2[1][k] = fma2(s1d, E[1][k], acc2[1][k]);
            }
        }

        // Store partials (natural float16 order).
#pragma unroll
        for (int bb = 0; bb < BPG; bb++) {
            float4* dst = (float4*)(g_partial +
                ((((size_t)chunk * BB + (b0 + bb)) * MM + tid) << 4));
#pragma unroll
            for (int q = 0; q < 4; q++) {
                float xx, yy, zz, ww;
                unpack2(acc2[bb][2 * q],     xx, yy);
                unpack2(acc2[bb][2 * q + 1], zz, ww);
                dst[q] = make_float4(xx, yy, zz, ww);
            }
        }
    } else {
        // ---------------- Reducer (warp 16) ----------------
        bar_arrive(BAR_RDY0 + 1);   // prime READY1 for producers' iteration 0
        for (int i = 0; i < CHUNK; i++) {
            const int buf = i & 1;
            bar_wait(BAR_FULL0 + buf);
#pragma unroll
            for (int bb = 0; bb < BPG; bb++) {
                const float4* eb = (const float4*)&ebuf[buf][bb][0];
                const float4 a = eb[lane], b = eb[lane + 32],
                             c = eb[lane + 64], d = eb[lane + 96];
                float s = (a.x + a.y + a.z + a.w) + (b.x + b.y + b.z + b.w)
                        + (c.x + c.y + c.z + c.w) + (d.x + d.y + d.z + d.w);
#pragma unroll
                for (int o = 16; o > 0; o >>= 1) s += __shfl_xor_sync(0xffffffffu, s, o);
                if (lane == 0) sS[buf][bb] = s;
            }
            bar_arrive(BAR_RDY0 + buf);
        }
    }

    // ---- Grid-wide barrier (all GRID CTAs resident -> deadlock-free). ----
    __threadfence();
    __syncthreads();
    if (tid == 0) {
        atomicAdd(&g_cnt1, 1u);
        while (atomicAdd(&g_cnt1, 0u) < GRID) { }
    }
    __syncthreads();
    __threadfence();

    // ---- Phase 2: LayerNorm (producer threads only; 1:1 mapping). ----
    if (tid < MM) {
        const int t   = blockIdx.x * MM + tid;   // 0 .. B*MM*8-1
        const int row = t >> 3;
        const int q   = t & 3;
        const int h   = (t >> 2) & 1;
        const int b   = row / MM;
        const int m   = row % MM;

        float4 v = make_float4(0.f, 0.f, 0.f, 0.f);
#pragma unroll
        for (int cc = 0; cc < NCHUNK / 2; cc++) {
            const int c = h * (NCHUNK / 2) + cc;
            const float4 p = *(const float4*)(g_partial +
                ((((size_t)c * BB + b) * MM + m) << 4) + q * 4);
            v.x += p.x; v.y += p.y; v.z += p.z; v.w += p.w;
        }
        v.x += __shfl_xor_sync(0xffffffffu, v.x, 4);
        v.y += __shfl_xor_sync(0xffffffffu, v.y, 4);
        v.z += __shfl_xor_sync(0xffffffffu, v.z, 4);
        v.w += __shfl_xor_sync(0xffffffffu, v.w, 4);

        float s = v.x + v.y + v.z + v.w;
        s += __shfl_xor_sync(0xffffffffu, s, 1);
        s += __shfl_xor_sync(0xffffffffu, s, 2);
        const float mu = s * (1.0f / 16.0f);

        const float d0 = v.x - mu, d1 = v.y - mu, d2 = v.z - mu, d3 = v.w - mu;
        float ss = d0 * d0 + d1 * d1 + d2 * d2 + d3 * d3;
        ss += __shfl_xor_sync(0xffffffffu, ss, 1);
        ss += __shfl_xor_sync(0xffffffffu, ss, 2);
        const float rs = rsqrtf(ss * (1.0f / 16.0f) + LN_EPS);

        if (h == 0) {
            const float4 gm = *(const float4*)(gamma + q * 4);
            const float4 bt = *(const float4*)(beta + q * 4);
            float4 o;
            o.x = d0 * rs * gm.x + bt.x;
            o.y = d1 * rs * gm.y + bt.y;
            o.z = d2 * rs * gm.z + bt.z;
            o.w = d3 * rs * gm.w + bt.w;
            *(float4*)(nv_out + (size_t)row * 16 + q * 4) = o;
        }
    }

    // ---- Counter self-reset (all CTAs past the spin before reset). ----
    __syncthreads();
    if (tid == 0) {
        const unsigned int r = atomicAdd(&g_cnt2, 1u);
        if (r == GRID - 1) {
            g_cnt1 = 0;
            g_cnt2 = 0;
            __threadfence();
        }
    }
}

extern "C" void kernel_launch(void* const* d_in, const int* in_sizes, int n_in,
                              void* d_out, int out_size)
{
    // metadata order: input, num_iter, w, V, gamma, beta
    const float* x     = (const float*)d_in[0];
    const float* w     = (const float*)d_in[2];
    const float* V     = (const float*)d_in[3];
    const float* gamma = (const float*)d_in[4];
    const float* beta  = (const float*)d_in[5];

    float* out    = (float*)d_out;
    float* nv_out = out;                          // [16,512,16]   = 131072
    float* agree  = out + (size_t)BB * MM * 16;   // [16,1024,512] = 8388608

    cudaFuncSetAttribute(caps_fused, cudaFuncAttributeMaxDynamicSharedMemorySize,
                         SM_TOTAL);
    caps_fused<<<GRID, THREADS, SM_TOTAL>>>(x, w, V, gamma, beta, nv_out, agree);
}

// round 11
// speedup vs baseline: 1.6738x; 1.6738x over previous
#include <cuda_runtime.h>
#include <cstdint>

#define BB     16
#define NIN    1024
#define MM     512
#define NCHUNK 16
#define CHUNK  (NIN / NCHUNK)   // 64
#define BPG    2                // batches per CTA (register budget bound)
#define LOG2E  1.4426950408889634f
#define LN_EPS 1e-5f

typedef unsigned long long u64;

// Deterministic per-chunk partial accumulators for nv: [chunk][b][m][16]
__device__ float g_partial[NCHUNK * BB * MM * 16];

__device__ __forceinline__ u64 pack2(float lo, float hi) {
    u64 r; asm("mov.b64 %0,{%1,%2};" : "=l"(r) : "f"(lo), "f"(hi)); return r;
}
__device__ __forceinline__ void unpack2(u64 v, float& lo, float& hi) {
    asm("mov.b64 {%0,%1},%2;" : "=f"(lo), "=f"(hi) : "l"(v));
}
__device__ __forceinline__ u64 fma2(u64 a, u64 b, u64 c) {
    u64 d; asm("fma.rn.f32x2 %0,%1,%2,%3;" : "=l"(d) : "l"(a), "l"(b), "l"(c)); return d;
}
__device__ __forceinline__ u64 add2(u64 a, u64 b) {
    u64 d; asm("add.rn.f32x2 %0,%1,%2;" : "=l"(d) : "l"(a), "l"(b)); return d;
}
__device__ __forceinline__ u64 mul2(u64 a, u64 b) {
    u64 d; asm("mul.rn.f32x2 %0,%1,%2;" : "=l"(d) : "l"(a), "l"(b)); return d;
}
__device__ __forceinline__ float ex2f(float x) {
    float y; asm("ex2.approx.f32 %0,%1;" : "=f"(y) : "f"(x)); return y;
}
__device__ __forceinline__ float rcpf(float x) {
    float y; asm("rcp.approx.f32 %0,%1;" : "=f"(y) : "f"(x)); return y;
}
__device__ __forceinline__ void stcs(float* p, float v) {
    asm volatile("st.global.cs.f32 [%0],%1;" :: "l"(p), "f"(v) : "memory");
}

// Round-4 flow (best so far) with two latency/issue fixes:
//  (1) post-barrier block sum via broadcast LDS.128 + scalar add tree
//      (~70-cyc chain) instead of the dependent LDS+4xSHFL+2xbcast chain
//      (~190 cyc, phase-locked across all 16 warps every iteration);
//  (2) xsd pose operands loaded as LDS.128 pairs (2 per 'a' row) halving
//      shared-load issue slots in the hot loop.
__global__ __launch_bounds__(512, 1)
void caps_main(const float* __restrict__ x,     // [B, NIN, 16]
               const float* __restrict__ w,     // [NIN, 4, 4, MM]
               const float* __restrict__ V,     // [MM, 16]
               float* __restrict__ agree_out)   // [B, NIN, MM]
{
    __shared__ __align__(16) u64  xsd[BPG][CHUNK][16];  // dup-packed, LOG2E-prescaled x
    __shared__ __align__(16) float sred[2][32];         // [buf][bb*16 + wid]

    const int tid   = threadIdx.x;          // m
    const int wid   = tid >> 5;
    const int lane  = tid & 31;
    const int chunk = blockIdx.x % NCHUNK;
    const int bp    = blockIdx.x / NCHUNK;  // 0..7
    const int b0    = bp * BPG;
    const int n0    = chunk * CHUNK;

    // Stage + rescale + duplicate x into shared.
    for (int idx = tid; idx < BPG * CHUNK * 16; idx += 512) {
        const int bb  = idx / (CHUNK * 16);
        const int rem = idx % (CHUNK * 16);
        const int i   = rem >> 4;
        const int j   = rem & 15;
        const float v = x[(((size_t)(b0 + bb) * NIN) + n0 + i) * 16 + j] * LOG2E;
        xsd[bb][i][j] = pack2(v, v);
    }

    // Packed initial query: Vq2[a*2+dp] = {V[m][a*4+2dp], V[m][a*4+2dp+1]}.
    u64 Vq2[8];
    {
        const float* vm = V + (size_t)tid * 16;
#pragma unroll
        for (int k = 0; k < 8; k++) Vq2[k] = pack2(vm[2 * k], vm[2 * k + 1]);
    }

    u64 acc2[BPG][8];
#pragma unroll
    for (int bb = 0; bb < BPG; bb++)
#pragma unroll
        for (int k = 0; k < 8; k++) acc2[bb][k] = 0ull;

    __syncthreads();

    const float* wbase = w + (size_t)n0 * (16 * MM) + tid;

    // Prefetch w for iteration 0.
    float wn[16];
#pragma unroll
    for (int s = 0; s < 16; s++) wn[s] = wbase[(size_t)s * MM];

    for (int i = 0; i < CHUNK; i++) {
        // Pack current w into d-pairs: wpair[x*2+dp] = {w[x*4+2dp], w[x*4+2dp+1]}.
        u64 wpair[8];
#pragma unroll
        for (int k = 0; k < 8; k++) wpair[k] = pack2(wn[2 * k], wn[2 * k + 1]);

        // Prefetch next iteration's w (hidden behind this iteration's math).
        if (i + 1 < CHUNK) {
            const float* wp = wbase + (size_t)(i + 1) * 16 * MM;
#pragma unroll
            for (int s = 0; s < 16; s++) wn[s] = wp[(size_t)s * MM];
        }

        u64 e2[BPG][8];
        float inv[BPG], eag[BPG];

#pragma unroll
        for (int bb = 0; bb < BPG; bb++) {
            // Pose transform: 32 packed FMA; xsd row 'a' fetched as 2x LDS.128.
            u64 t2[8];
#pragma unroll
            for (int a = 0; a < 4; a++) {
                const uint4 xu0 = *(const uint4*)&xsd[bb][i][a * 4 + 0]; // x0,x1
                const uint4 xu1 = *(const uint4*)&xsd[bb][i][a * 4 + 2]; // x2,x3
                const u64 xa0 = ((u64)xu0.y << 32) | xu0.x;
                const u64 xa1 = ((u64)xu0.w << 32) | xu0.z;
                const u64 xa2 = ((u64)xu1.y << 32) | xu1.x;
                const u64 xa3 = ((u64)xu1.w << 32) | xu1.z;
#pragma unroll
                for (int dp = 0; dp < 2; dp++) {
                    u64 acc = mul2(xa0, wpair[0 * 2 + dp]);
                    acc = fma2(xa1, wpair[1 * 2 + dp], acc);
                    acc = fma2(xa2, wpair[2 * 2 + dp], acc);
                    acc = fma2(xa3, wpair[3 * 2 + dp], acc);
                    t2[a * 2 + dp] = acc;
                }
            }
            // exp (log2-domain): unpack -> ex2 -> repack.
#pragma unroll
            for (int k = 0; k < 8; k++) {
                float lo, hi; unpack2(t2[k], lo, hi);
                e2[bb][k] = pack2(ex2f(lo), ex2f(hi));
            }
            // Inner-softmax denominator.
            u64 s01 = add2(add2(e2[bb][0], e2[bb][1]), add2(e2[bb][2], e2[bb][3]));
            u64 s23 = add2(add2(e2[bb][4], e2[bb][5]), add2(e2[bb][6], e2[bb][7]));
            u64 st  = add2(s01, s23);
            float slo, shi; unpack2(st, slo, shi);
            inv[bb] = rcpf(slo + shi);
            // Agreement dot with Vq.
            u64 g = mul2(e2[bb][0], Vq2[0]);
#pragma unroll
            for (int k = 1; k < 8; k++) g = fma2(e2[bb][k], Vq2[k], g);
            float glo, ghi; unpack2(g, glo, ghi);
            const float ag = (glo + ghi) * inv[bb];
            stcs(agree_out + (((size_t)(b0 + bb) * NIN) + n0 + i) * MM + tid, ag);
            eag[bb] = ex2f(ag * LOG2E);   // |ag| <= 1, max-free softmax safe
        }

        // Pre-barrier: per-warp partials of exp(ag) for both b's.
        float v0 = eag[0], v1 = eag[1];
#pragma unroll
        for (int o = 16; o > 0; o >>= 1) {
            v0 += __shfl_xor_sync(0xffffffffu, v0, o);
            v1 += __shfl_xor_sync(0xffffffffu, v1, o);
        }
        const int buf = i & 1;
        if (lane == 0) { sred[buf][wid] = v0; sred[buf][16 + wid] = v1; }
        __syncthreads();

        // Post-barrier: every thread sums the 32 partials via 8 broadcast
        // LDS.128 + scalar add tree (short dependency chain; bit-identical
        // result across threads).
        const float4* sp = (const float4*)&sred[buf][0];
        const float4 p0 = sp[0], p1 = sp[1], p2 = sp[2], p3 = sp[3];
        const float4 p4 = sp[4], p5 = sp[5], p6 = sp[6], p7 = sp[7];
        const float S0 = (((p0.x + p0.y) + (p0.z + p0.w)) +
                          ((p1.x + p1.y) + (p1.z + p1.w))) +
                         (((p2.x + p2.y) + (p2.z + p2.w)) +
                          ((p3.x + p3.y) + (p3.z + p3.w)));
        const float S1 = (((p4.x + p4.y) + (p4.z + p4.w)) +
                          ((p5.x + p5.y) + (p5.z + p5.w))) +
                         (((p6.x + p6.y) + (p6.z + p6.w)) +
                          ((p7.x + p7.y) + (p7.z + p7.w)));

        const float q0 = eag[0] * rcpf(S0) * inv[0];
        const float q1 = eag[1] * rcpf(S1) * inv[1];
        const u64 q0d = pack2(q0, q0);
        const u64 q1d = pack2(q1, q1);
#pragma unroll
        for (int k = 0; k < 8; k++) {
            acc2[0][k] = fma2(q0d, e2[0][k], acc2[0][k]);
            acc2[1][k] = fma2(q1d, e2[1][k], acc2[1][k]);
        }
    }

    // acc2[bb] as u64[8] is already float[16] in natural slot order.
#pragma unroll
    for (int bb = 0; bb < BPG; bb++) {
        float4* dst = (float4*)(g_partial +
            ((((size_t)chunk * BB + (b0 + bb)) * MM + tid) << 4));
#pragma unroll
        for (int q = 0; q < 4; q++) {
            float xx, yy, zz, ww;
            unpack2(acc2[bb][2 * q],     xx, yy);
            unpack2(acc2[bb][2 * q + 1], zz, ww);
            dst[q] = make_float4(xx, yy, zz, ww);
        }
    }
}

// Reduce chunk partials + LayerNorm. 8 lanes cooperate per (b,m) row:
// q = float4 quarter (0..3), h = chunk half (0..1).
__global__ __launch_bounds__(256)
void caps_ln(const float* __restrict__ gamma,
             const float* __restrict__ beta,
             float* __restrict__ nv_out)  // [B*MM, 16]
{
    const int t   = blockIdx.x * 256 + threadIdx.x;  // 0 .. B*MM*8-1
    const int row = t >> 3;
    const int q   = t & 3;
    const int h   = (t >> 2) & 1;
    const int b   = row / MM;
    const int m   = row % MM;

    float4 v = make_float4(0.f, 0.f, 0.f, 0.f);
#pragma unroll
    for (int cc = 0; cc < NCHUNK / 2; cc++) {
        const int c = h * (NCHUNK / 2) + cc;
        const float4 p = *(const float4*)(g_partial +
            ((((size_t)c * BB + b) * MM + m) << 4) + q * 4);
        v.x += p.x; v.y += p.y; v.z += p.z; v.w += p.w;
    }
    // Combine chunk halves (lanes differ in bit 2).
    v.x += __shfl_xor_sync(0xffffffffu, v.x, 4);
    v.y += __shfl_xor_sync(0xffffffffu, v.y, 4);
    v.z += __shfl_xor_sync(0xffffffffu, v.z, 4);
    v.w += __shfl_xor_sync(0xffffffffu, v.w, 4);

    // Row stats across the 4 q-lanes (bits 0-1).
    float s = v.x + v.y + v.z + v.w;
    s += __shfl_xor_sync(0xffffffffu, s, 1);
    s += __shfl_xor_sync(0xffffffffu, s, 2);
    const float mu = s * (1.0f / 16.0f);

    const float d0 = v.x - mu, d1 = v.y - mu, d2 = v.z - mu, d3 = v.w - mu;
    float ss = d0 * d0 + d1 * d1 + d2 * d2 + d3 * d3;
    ss += __shfl_xor_sync(0xffffffffu, ss, 1);
    ss += __shfl_xor_sync(0xffffffffu, ss, 2);
    const float rs = rsqrtf(ss * (1.0f / 16.0f) + LN_EPS);

    if (h == 0) {
        const float4 gm = *(const float4*)(gamma + q * 4);
        const float4 bt = *(const float4*)(beta + q * 4);
        float4 o;
        o.x = d0 * rs * gm.x + bt.x;
        o.y = d1 * rs * gm.y + bt.y;
        o.z = d2 * rs * gm.z + bt.z;
        o.w = d3 * rs * gm.w + bt.w;
        *(float4*)(nv_out + (size_t)row * 16 + q * 4) = o;
    }
}

extern "C" void kernel_launch(void* const* d_in, const int* in_sizes, int n_in,
                              void* d_out, int out_size)
{
    // metadata order: input, num_iter, w, V, gamma, beta
    const float* x     = (const float*)d_in[0];
    const float* w     = (const float*)d_in[2];
    const float* V     = (const float*)d_in[3];
    const float* gamma = (const float*)d_in[4];
    const float* beta  = (const float*)d_in[5];

    float* out    = (float*)d_out;
    float* nv_out = out;                          // [16,512,16]   = 131072
    float* agree  = out + (size_t)BB * MM * 16;   // [16,1024,512] = 8388608

    caps_main<<<NCHUNK * (BB / BPG), 512>>>(x, w, V, agree);
    caps_ln<<<(BB * MM * 8) / 256, 256>>>(gamma, beta, nv_out);
}

// round 13
// speedup vs baseline: 2.0279x; 1.2115x over previous
#include <cuda_runtime.h>
#include <cstdint>

#define BB     16
#define NIN    1024
#define MM     512
#define NCHUNK 16
#define CHUNK  (NIN / NCHUNK)   // 64
#define BPG    2                // batches per CTA (register budget bound)
#define LOG2E  1.4426950408889634f
#define LN_EPS 1e-5f

typedef unsigned long long u64;

// Deterministic per-chunk partial accumulators for nv: [chunk][b][m][16]
__device__ float g_partial[NCHUNK * BB * MM * 16];

__device__ __forceinline__ u64 pack2(float lo, float hi) {
    u64 r; asm("mov.b64 %0,{%1,%2};" : "=l"(r) : "f"(lo), "f"(hi)); return r;
}
__device__ __forceinline__ void unpack2(u64 v, float& lo, float& hi) {
    asm("mov.b64 {%0,%1},%2;" : "=f"(lo), "=f"(hi) : "l"(v));
}
__device__ __forceinline__ u64 fma2(u64 a, u64 b, u64 c) {
    u64 d; asm("fma.rn.f32x2 %0,%1,%2,%3;" : "=l"(d) : "l"(a), "l"(b), "l"(c)); return d;
}
__device__ __forceinline__ u64 add2(u64 a, u64 b) {
    u64 d; asm("add.rn.f32x2 %0,%1,%2;" : "=l"(d) : "l"(a), "l"(b)); return d;
}
__device__ __forceinline__ u64 mul2(u64 a, u64 b) {
    u64 d; asm("mul.rn.f32x2 %0,%1,%2;" : "=l"(d) : "l"(a), "l"(b)); return d;
}
__device__ __forceinline__ float ex2f(float x) {
    float y; asm("ex2.approx.f32 %0,%1;" : "=f"(y) : "f"(x)); return y;
}
__device__ __forceinline__ float rcpf(float x) {
    float y; asm("rcp.approx.f32 %0,%1;" : "=f"(y) : "f"(x)); return y;
}
__device__ __forceinline__ void stcs(float* p, float v) {
    asm volatile("st.global.cs.f32 [%0],%1;" :: "l"(p), "f"(v) : "memory");
}
// Packed fp16 exp2: converts an f32x2 (log2-domain) to f16x2, does ONE MUFU
// ex2 for both halves, converts back to two f32. Halves the dominant MUFU
// term (16 inner exps/bb -> 8).
__device__ __forceinline__ u64 ex2_f16x2_pair(u64 t) {
    float lo, hi;
    unpack2(t, lo, hi);
    unsigned int h, eh;
    asm("cvt.rn.f16x2.f32 %0,%1,%2;" : "=r"(h) : "f"(hi), "f"(lo)); // hi->msb, lo->lsb
    asm("ex2.approx.f16x2 %0,%1;" : "=r"(eh) : "r"(h));
    float elo, ehi;
    asm("{\n\t.reg .b16 l,u;\n\tmov.b32 {l,u},%2;\n\t"
        "cvt.f32.f16 %0,l;\n\tcvt.f32.f16 %1,u;\n\t}"
        : "=f"(elo), "=f"(ehi) : "r"(eh));
    return pack2(elo, ehi);
}

// EXACT round-4 flow (best: 92.2us) with ONE change: the 16 inner-softmax
// exps per bb run through ex2.approx.f16x2 (one MUFU op per f32x2 pair)
// instead of two ex2.approx.f32. MUFU demand/thread-iter drops 37 -> 21.
// All other math (sums, agreement, qk softmax, accumulation) stays f32.
__global__ __launch_bounds__(512, 1)
void caps_main(const float* __restrict__ x,     // [B, NIN, 16]
               const float* __restrict__ w,     // [NIN, 4, 4, MM]
               const float* __restrict__ V,     // [MM, 16]
               float* __restrict__ agree_out)   // [B, NIN, MM]
{
    __shared__ u64  xsd[BPG][CHUNK][16];  // dup-packed, LOG2E-prescaled x (16 KB)
    __shared__ float sred[2][32];         // [buf][bb*16 + wid]

    const int tid   = threadIdx.x;          // m
    const int wid   = tid >> 5;
    const int lane  = tid & 31;
    const int chunk = blockIdx.x % NCHUNK;
    const int bp    = blockIdx.x / NCHUNK;  // 0..7
    const int b0    = bp * BPG;
    const int n0    = chunk * CHUNK;

    // Stage + rescale + duplicate x into shared.
    for (int idx = tid; idx < BPG * CHUNK * 16; idx += 512) {
        const int bb  = idx / (CHUNK * 16);
        const int rem = idx % (CHUNK * 16);
        const int i   = rem >> 4;
        const int j   = rem & 15;
        const float v = x[(((size_t)(b0 + bb) * NIN) + n0 + i) * 16 + j] * LOG2E;
        xsd[bb][i][j] = pack2(v, v);
    }

    // Packed initial query: Vq2[a*2+dp] = {V[m][a*4+2dp], V[m][a*4+2dp+1]}.
    u64 Vq2[8];
    {
        const float* vm = V + (size_t)tid * 16;
#pragma unroll
        for (int k = 0; k < 8; k++) Vq2[k] = pack2(vm[2 * k], vm[2 * k + 1]);
    }

    u64 acc2[BPG][8];
#pragma unroll
    for (int bb = 0; bb < BPG; bb++)
#pragma unroll
        for (int k = 0; k < 8; k++) acc2[bb][k] = 0ull;

    __syncthreads();

    const float* wbase = w + (size_t)n0 * (16 * MM) + tid;

    // Prefetch w for iteration 0.
    float wn[16];
#pragma unroll
    for (int s = 0; s < 16; s++) wn[s] = wbase[(size_t)s * MM];

    for (int i = 0; i < CHUNK; i++) {
        // Pack current w into d-pairs: wpair[x*2+dp] = {w[x*4+2dp], w[x*4+2dp+1]}.
        u64 wpair[8];
#pragma unroll
        for (int k = 0; k < 8; k++) wpair[k] = pack2(wn[2 * k], wn[2 * k + 1]);

        // Prefetch next iteration's w (hidden behind this iteration's math).
        if (i + 1 < CHUNK) {
            const float* wp = wbase + (size_t)(i + 1) * 16 * MM;
#pragma unroll
            for (int s = 0; s < 16; s++) wn[s] = wp[(size_t)s * MM];
        }

        u64 e2[BPG][8];
        float inv[BPG], eag[BPG];

#pragma unroll
        for (int bb = 0; bb < BPG; bb++) {
            // Pose transform: 32 packed FMA.
            u64 t2[8];
#pragma unroll
            for (int a = 0; a < 4; a++) {
#pragma unroll
                for (int dp = 0; dp < 2; dp++) {
                    u64 acc = mul2(xsd[bb][i][a * 4 + 0], wpair[0 * 2 + dp]);
                    acc = fma2(xsd[bb][i][a * 4 + 1], wpair[1 * 2 + dp], acc);
                    acc = fma2(xsd[bb][i][a * 4 + 2], wpair[2 * 2 + dp], acc);
                    acc = fma2(xsd[bb][i][a * 4 + 3], wpair[3 * 2 + dp], acc);
                    t2[a * 2 + dp] = acc;
                }
            }
            // exp (log2-domain) via packed fp16 MUFU: one ex2 per f32x2 pair.
#pragma unroll
            for (int k = 0; k < 8; k++)
                e2[bb][k] = ex2_f16x2_pair(t2[k]);
            // Inner-softmax denominator.
            u64 s01 = add2(add2(e2[bb][0], e2[bb][1]), add2(e2[bb][2], e2[bb][3]));
            u64 s23 = add2(add2(e2[bb][4], e2[bb][5]), add2(e2[bb][6], e2[bb][7]));
            u64 st  = add2(s01, s23);
            float slo, shi; unpack2(st, slo, shi);
            inv[bb] = rcpf(slo + shi);
            // Agreement dot with Vq (f32).
            u64 g = mul2(e2[bb][0], Vq2[0]);
#pragma unroll
            for (int k = 1; k < 8; k++) g = fma2(e2[bb][k], Vq2[k], g);
            float glo, ghi; unpack2(g, glo, ghi);
            const float ag = (glo + ghi) * inv[bb];
            stcs(agree_out + (((size_t)(b0 + bb) * NIN) + n0 + i) * MM + tid, ag);
            eag[bb] = ex2f(ag * LOG2E);   // |ag| <= 1, max-free softmax safe (f32)
        }

        // Block-wide sums of exp(ag) for both b's; one barrier, double-buffered.
        float v0 = eag[0], v1 = eag[1];
#pragma unroll
        for (int o = 16; o > 0; o >>= 1) {
            v0 += __shfl_xor_sync(0xffffffffu, v0, o);
            v1 += __shfl_xor_sync(0xffffffffu, v1, o);
        }
        const int buf = i & 1;
        if (lane == 0) { sred[buf][wid] = v0; sred[buf][16 + wid] = v1; }
        __syncthreads();
        // Every warp redundantly reduces: lanes 0-15 -> bb0, 16-31 -> bb1.
        float z = sred[buf][lane];
#pragma unroll
        for (int o = 8; o > 0; o >>= 1) z += __shfl_xor_sync(0xffffffffu, z, o);
        const float S0 = __shfl_sync(0xffffffffu, z, 0);
        const float S1 = __shfl_sync(0xffffffffu, z, 16);

        const float q0 = eag[0] * rcpf(S0) * inv[0];
        const float q1 = eag[1] * rcpf(S1) * inv[1];
        const u64 q0d = pack2(q0, q0);
        const u64 q1d = pack2(q1, q1);
#pragma unroll
        for (int k = 0; k < 8; k++) {
            acc2[0][k] = fma2(q0d, e2[0][k], acc2[0][k]);
            acc2[1][k] = fma2(q1d, e2[1][k], acc2[1][k]);
        }
    }

    // acc2[bb] as u64[8] is already float[16] in natural slot order.
#pragma unroll
    for (int bb = 0; bb < BPG; bb++) {
        float4* dst = (float4*)(g_partial +
            ((((size_t)chunk * BB + (b0 + bb)) * MM + tid) << 4));
#pragma unroll
        for (int q = 0; q < 4; q++) {
            float xx, yy, zz, ww;
            unpack2(acc2[bb][2 * q],     xx, yy);
            unpack2(acc2[bb][2 * q + 1], zz, ww);
            dst[q] = make_float4(xx, yy, zz, ww);
        }
    }
}

// Reduce chunk partials + LayerNorm. 8 lanes cooperate per (b,m) row:
// q = float4 quarter (0..3), h = chunk half (0..1).
__global__ __launch_bounds__(256)
void caps_ln(const float* __restrict__ gamma,
             const float* __restrict__ beta,
             float* __restrict__ nv_out)  // [B*MM, 16]
{
    const int t   = blockIdx.x * 256 + threadIdx.x;  // 0 .. B*MM*8-1
    const int row = t >> 3;
    const int q   = t & 3;
    const int h   = (t >> 2) & 1;
    const int b   = row / MM;
    const int m   = row % MM;

    float4 v = make_float4(0.f, 0.f, 0.f, 0.f);
#pragma unroll
    for (int cc = 0; cc < NCHUNK / 2; cc++) {
        const int c = h * (NCHUNK / 2) + cc;
        const float4 p = *(const float4*)(g_partial +
            ((((size_t)c * BB + b) * MM + m) << 4) + q * 4);
        v.x += p.x; v.y += p.y; v.z += p.z; v.w += p.w;
    }
    // Combine chunk halves (lanes differ in bit 2).
    v.x += __shfl_xor_sync(0xffffffffu, v.x, 4);
    v.y += __shfl_xor_sync(0xffffffffu, v.y, 4);
    v.z += __shfl_xor_sync(0xffffffffu, v.z, 4);
    v.w += __shfl_xor_sync(0xffffffffu, v.w, 4);

    // Row stats across the 4 q-lanes (bits 0-1).
    float s = v.x + v.y + v.z + v.w;
    s += __shfl_xor_sync(0xffffffffu, s, 1);
    s += __shfl_xor_sync(0xffffffffu, s, 2);
    const float mu = s * (1.0f / 16.0f);

    const float d0 = v.x - mu, d1 = v.y - mu, d2 = v.z - mu, d3 = v.w - mu;
    float ss = d0 * d0 + d1 * d1 + d2 * d2 + d3 * d3;
    ss += __shfl_xor_sync(0xffffffffu, ss, 1);
    ss += __shfl_xor_sync(0xffffffffu, ss, 2);
    const float rs = rsqrtf(ss * (1.0f / 16.0f) + LN_EPS);

    if (h == 0) {
        const float4 gm = *(const float4*)(gamma + q * 4);
        const float4 bt = *(const float4*)(beta + q * 4);
        float4 o;
        o.x = d0 * rs * gm.x + bt.x;
        o.y = d1 * rs * gm.y + bt.y;
        o.z = d2 * rs * gm.z + bt.z;
        o.w = d3 * rs * gm.w + bt.w;
        *(float4*)(nv_out + (size_t)row * 16 + q * 4) = o;
    }
}

extern "C" void kernel_launch(void* const* d_in, const int* in_sizes, int n_in,
                              void* d_out, int out_size)
{
    // metadata order: input, num_iter, w, V, gamma, beta
    const float* x     = (const float*)d_in[0];
    const float* w     = (const float*)d_in[2];
    const float* V     = (const float*)d_in[3];
    const float* gamma = (const float*)d_in[4];
    const float* beta  = (const float*)d_in[5];

    float* out    = (float*)d_out;
    float* nv_out = out;                          // [16,512,16]   = 131072
    float* agree  = out + (size_t)BB * MM * 16;   // [16,1024,512] = 8388608

    caps_main<<<NCHUNK * (BB / BPG), 512>>>(x, w, V, agree);
    caps_ln<<<(BB * MM * 8) / 256, 256>>>(gamma, beta, nv_out);
}

// round 14
// speedup vs baseline: 2.0694x; 1.0205x over previous
#include <cuda_runtime.h>
#include <cstdint>

#define BB     16
#define NIN    1024
#define MM     512
#define NCHUNK 18                 // 16 chunks of 57 + 2 of 56 = 1024
#define CH_BIG 57
#define BPG    2                  // batches per CTA (register budget bound)
#define LOG2E  1.4426950408889634f
#define LN_EPS 1e-5f

typedef unsigned long long u64;

// Deterministic per-chunk partial accumulators for nv: [chunk][b][m][16]
__device__ float g_partial[NCHUNK * BB * MM * 16];

__device__ __forceinline__ u64 pack2(float lo, float hi) {
    u64 r; asm("mov.b64 %0,{%1,%2};" : "=l"(r) : "f"(lo), "f"(hi)); return r;
}
__device__ __forceinline__ void unpack2(u64 v, float& lo, float& hi) {
    asm("mov.b64 {%0,%1},%2;" : "=f"(lo), "=f"(hi) : "l"(v));
}
__device__ __forceinline__ u64 fma2(u64 a, u64 b, u64 c) {
    u64 d; asm("fma.rn.f32x2 %0,%1,%2,%3;" : "=l"(d) : "l"(a), "l"(b), "l"(c)); return d;
}
__device__ __forceinline__ u64 add2(u64 a, u64 b) {
    u64 d; asm("add.rn.f32x2 %0,%1,%2;" : "=l"(d) : "l"(a), "l"(b)); return d;
}
__device__ __forceinline__ u64 mul2(u64 a, u64 b) {
    u64 d; asm("mul.rn.f32x2 %0,%1,%2;" : "=l"(d) : "l"(a), "l"(b)); return d;
}
__device__ __forceinline__ float ex2f(float x) {
    float y; asm("ex2.approx.f32 %0,%1;" : "=f"(y) : "f"(x)); return y;
}
__device__ __forceinline__ float rcpf(float x) {
    float y; asm("rcp.approx.f32 %0,%1;" : "=f"(y) : "f"(x)); return y;
}
__device__ __forceinline__ void stcs(float* p, float v) {
    asm volatile("st.global.cs.f32 [%0],%1;" :: "l"(p), "f"(v) : "memory");
}
// Packed fp16 exp2: one MUFU ex2 for both halves of an f32x2 (round-13 win).
__device__ __forceinline__ u64 ex2_f16x2_pair(u64 t) {
    float lo, hi;
    unpack2(t, lo, hi);
    unsigned int h, eh;
    asm("cvt.rn.f16x2.f32 %0,%1,%2;" : "=r"(h) : "f"(hi), "f"(lo)); // hi->msb, lo->lsb
    asm("ex2.approx.f16x2 %0,%1;" : "=r"(eh) : "r"(h));
    float elo, ehi;
    asm("{\n\t.reg .b16 l,u;\n\tmov.b32 {l,u},%2;\n\t"
        "cvt.f32.f16 %0,l;\n\tcvt.f32.f16 %1,u;\n\t}"
        : "=f"(elo), "=f"(ehi) : "r"(eh));
    return pack2(elo, ehi);
}

// Chunk partitioning: chunks 0..15 have 57 rows, chunks 16..17 have 56.
__device__ __host__ __forceinline__ int chunk_start(int c) {
    return (c < 16) ? (CH_BIG * c) : (912 + 56 * (c - 16));
}
__device__ __host__ __forceinline__ int chunk_len(int c) {
    return (c < 16) ? CH_BIG : 56;
}

// Round-13 winner flow, repartitioned from 16 even chunks (128 CTAs) to 18
// uneven chunks (144 CTAs) so only 4 of 148 SMs idle instead of 20. Makespan
// scales with max chunk: 57/64 -> ~11% faster main kernel.
__global__ __launch_bounds__(512, 1)
void caps_main(const float* __restrict__ x,     // [B, NIN, 16]
               const float* __restrict__ w,     // [NIN, 4, 4, MM]
               const float* __restrict__ V,     // [MM, 16]
               float* __restrict__ agree_out)   // [B, NIN, MM]
{
    __shared__ u64  xsd[BPG][CH_BIG][16];  // dup-packed, LOG2E-prescaled x
    __shared__ float sred[2][32];          // [buf][bb*16 + wid]

    const int tid   = threadIdx.x;          // m
    const int wid   = tid >> 5;
    const int lane  = tid & 31;
    const int chunk = blockIdx.x % NCHUNK;
    const int bp    = blockIdx.x / NCHUNK;  // 0..7
    const int b0    = bp * BPG;
    const int n0    = chunk_start(chunk);
    const int len   = chunk_len(chunk);

    // Stage + rescale + duplicate x into shared.
    for (int idx = tid; idx < BPG * len * 16; idx += 512) {
        const int bb  = idx / (len * 16);
        const int rem = idx % (len * 16);
        const int i   = rem >> 4;
        const int j   = rem & 15;
        const float v = x[(((size_t)(b0 + bb) * NIN) + n0 + i) * 16 + j] * LOG2E;
        xsd[bb][i][j] = pack2(v, v);
    }

    // Packed initial query: Vq2[a*2+dp] = {V[m][a*4+2dp], V[m][a*4+2dp+1]}.
    u64 Vq2[8];
    {
        const float* vm = V + (size_t)tid * 16;
#pragma unroll
        for (int k = 0; k < 8; k++) Vq2[k] = pack2(vm[2 * k], vm[2 * k + 1]);
    }

    u64 acc2[BPG][8];
#pragma unroll
    for (int bb = 0; bb < BPG; bb++)
#pragma unroll
        for (int k = 0; k < 8; k++) acc2[bb][k] = 0ull;

    __syncthreads();

    const float* wbase = w + (size_t)n0 * (16 * MM) + tid;

    // Prefetch w for iteration 0.
    float wn[16];
#pragma unroll
    for (int s = 0; s < 16; s++) wn[s] = wbase[(size_t)s * MM];

    for (int i = 0; i < len; i++) {
        // Pack current w into d-pairs: wpair[x*2+dp] = {w[x*4+2dp], w[x*4+2dp+1]}.
        u64 wpair[8];
#pragma unroll
        for (int k = 0; k < 8; k++) wpair[k] = pack2(wn[2 * k], wn[2 * k + 1]);

        // Prefetch next iteration's w (hidden behind this iteration's math).
        if (i + 1 < len) {
            const float* wp = wbase + (size_t)(i + 1) * 16 * MM;
#pragma unroll
            for (int s = 0; s < 16; s++) wn[s] = wp[(size_t)s * MM];
        }

        u64 e2[BPG][8];
        float inv[BPG], eag[BPG];

#pragma unroll
        for (int bb = 0; bb < BPG; bb++) {
            // Pose transform: 32 packed FMA.
            u64 t2[8];
#pragma unroll
            for (int a = 0; a < 4; a++) {
#pragma unroll
                for (int dp = 0; dp < 2; dp++) {
                    u64 acc = mul2(xsd[bb][i][a * 4 + 0], wpair[0 * 2 + dp]);
                    acc = fma2(xsd[bb][i][a * 4 + 1], wpair[1 * 2 + dp], acc);
                    acc = fma2(xsd[bb][i][a * 4 + 2], wpair[2 * 2 + dp], acc);
                    acc = fma2(xsd[bb][i][a * 4 + 3], wpair[3 * 2 + dp], acc);
                    t2[a * 2 + dp] = acc;
                }
            }
            // exp (log2-domain) via packed fp16 MUFU: one ex2 per f32x2 pair.
#pragma unroll
            for (int k = 0; k < 8; k++)
                e2[bb][k] = ex2_f16x2_pair(t2[k]);
            // Inner-softmax denominator.
            u64 s01 = add2(add2(e2[bb][0], e2[bb][1]), add2(e2[bb][2], e2[bb][3]));
            u64 s23 = add2(add2(e2[bb][4], e2[bb][5]), add2(e2[bb][6], e2[bb][7]));
            u64 st  = add2(s01, s23);
            float slo, shi; unpack2(st, slo, shi);
            inv[bb] = rcpf(slo + shi);
            // Agreement dot with Vq (f32).
            u64 g = mul2(e2[bb][0], Vq2[0]);
#pragma unroll
            for (int k = 1; k < 8; k++) g = fma2(e2[bb][k], Vq2[k], g);
            float glo, ghi; unpack2(g, glo, ghi);
            const float ag = (glo + ghi) * inv[bb];
            stcs(agree_out + (((size_t)(b0 + bb) * NIN) + n0 + i) * MM + tid, ag);
            eag[bb] = ex2f(ag * LOG2E);   // |ag| <= 1, max-free softmax safe (f32)
        }

        // Block-wide sums of exp(ag) for both b's; one barrier, double-buffered.
        float v0 = eag[0], v1 = eag[1];
#pragma unroll
        for (int o = 16; o > 0; o >>= 1) {
            v0 += __shfl_xor_sync(0xffffffffu, v0, o);
            v1 += __shfl_xor_sync(0xffffffffu, v1, o);
        }
        const int buf = i & 1;
        if (lane == 0) { sred[buf][wid] = v0; sred[buf][16 + wid] = v1; }
        __syncthreads();
        // Every warp redundantly reduces: lanes 0-15 -> bb0, 16-31 -> bb1.
        float z = sred[buf][lane];
#pragma unroll
        for (int o = 8; o > 0; o >>= 1) z += __shfl_xor_sync(0xffffffffu, z, o);
        const float S0 = __shfl_sync(0xffffffffu, z, 0);
        const float S1 = __shfl_sync(0xffffffffu, z, 16);

        const float q0 = eag[0] * rcpf(S0) * inv[0];
        const float q1 = eag[1] * rcpf(S1) * inv[1];
        const u64 q0d = pack2(q0, q0);
        const u64 q1d = pack2(q1, q1);
#pragma unroll
        for (int k = 0; k < 8; k++) {
            acc2[0][k] = fma2(q0d, e2[0][k], acc2[0][k]);
            acc2[1][k] = fma2(q1d, e2[1][k], acc2[1][k]);
        }
    }

    // acc2[bb] as u64[8] is already float[16] in natural slot order.
#pragma unroll
    for (int bb = 0; bb < BPG; bb++) {
        float4* dst = (float4*)(g_partial +
            ((((size_t)chunk * BB + (b0 + bb)) * MM + tid) << 4));
#pragma unroll
        for (int q = 0; q < 4; q++) {
            float xx, yy, zz, ww;
            unpack2(acc2[bb][2 * q],     xx, yy);
            unpack2(acc2[bb][2 * q + 1], zz, ww);
            dst[q] = make_float4(xx, yy, zz, ww);
        }
    }
}

// Reduce chunk partials + LayerNorm. 8 lanes cooperate per (b,m) row:
// q = float4 quarter (0..3), h = chunk half (0..1; 9 chunks each).
__global__ __launch_bounds__(256)
void caps_ln(const float* __restrict__ gamma,
             const float* __restrict__ beta,
             float* __restrict__ nv_out)  // [B*MM, 16]
{
    const int t   = blockIdx.x * 256 + threadIdx.x;  // 0 .. B*MM*8-1
    const int row = t >> 3;
    const int q   = t & 3;
    const int h   = (t >> 2) & 1;
    const int b   = row / MM;
    const int m   = row % MM;

    float4 v = make_float4(0.f, 0.f, 0.f, 0.f);
#pragma unroll
    for (int cc = 0; cc < NCHUNK / 2; cc++) {
        const int c = h * (NCHUNK / 2) + cc;
        const float4 p = *(const float4*)(g_partial +
            ((((size_t)c * BB + b) * MM + m) << 4) + q * 4);
        v.x += p.x; v.y += p.y; v.z += p.z; v.w += p.w;
    }
    // Combine chunk halves (lanes differ in bit 2).
    v.x += __shfl_xor_sync(0xffffffffu, v.x, 4);
    v.y += __shfl_xor_sync(0xffffffffu, v.y, 4);
    v.z += __shfl_xor_sync(0xffffffffu, v.z, 4);
    v.w += __shfl_xor_sync(0xffffffffu, v.w, 4);

    // Row stats across the 4 q-lanes (bits 0-1).
    float s = v.x + v.y + v.z + v.w;
    s += __shfl_xor_sync(0xffffffffu, s, 1);
    s += __shfl_xor_sync(0xffffffffu, s, 2);
    const float mu = s * (1.0f / 16.0f);

    const float d0 = v.x - mu, d1 = v.y - mu, d2 = v.z - mu, d3 = v.w - mu;
    float ss = d0 * d0 + d1 * d1 + d2 * d2 + d3 * d3;
    ss += __shfl_xor_sync(0xffffffffu, ss, 1);
    ss += __shfl_xor_sync(0xffffffffu, ss, 2);
    const float rs = rsqrtf(ss * (1.0f / 16.0f) + LN_EPS);

    if (h == 0) {
        const float4 gm = *(const float4*)(gamma + q * 4);
        const float4 bt = *(const float4*)(beta + q * 4);
        float4 o;
        o.x = d0 * rs * gm.x + bt.x;
        o.y = d1 * rs * gm.y + bt.y;
        o.z = d2 * rs * gm.z + bt.z;
        o.w = d3 * rs * gm.w + bt.w;
        *(float4*)(nv_out + (size_t)row * 16 + q * 4) = o;
    }
}

extern "C" void kernel_launch(void* const* d_in, const int* in_sizes, int n_in,
                              void* d_out, int out_size)
{
    // metadata order: input, num_iter, w, V, gamma, beta
    const float* x     = (const float*)d_in[0];
    const float* w     = (const float*)d_in[2];
    const float* V     = (const float*)d_in[3];
    const float* gamma = (const float*)d_in[4];
    const float* beta  = (const float*)d_in[5];

    float* out    = (float*)d_out;
    float* nv_out = out;                          // [16,512,16]   = 131072
    float* agree  = out + (size_t)BB * MM * 16;   // [16,1024,512] = 8388608

    caps_main<<<NCHUNK * (BB / BPG), 512>>>(x, w, V, agree);
    caps_ln<<<(BB * MM * 8) / 256, 256>>>(gamma, beta, nv_out);
}